// round 1
// baseline (speedup 1.0000x reference)
#include <cuda_runtime.h>
#include <cuda_bf16.h>

// Problem constants
#define BB      256
#define TENC    25
#define XDIM_   512
#define SDIM_   512
#define ADIM_   512
#define YDIM_   6625
#define TDEC    25
#define EMBIN   300

// ---------------------------------------------------------------------------
// Static device scratch (allocation-free rule: __device__ globals)
// ---------------------------------------------------------------------------
__device__ __align__(256) float g_Wcat[2048 * 512];      // [sEmbed_w ; gru_w_hh]
__device__ __align__(256) float g_bcat[2048];
__device__ __align__(256) float g_EbufPart[16 * 256 * 300];
__device__ __align__(256) float g_emb[256 * 300];
__device__ __align__(256) float g_XP[6400 * 512];        // xProj, row = b*25+t
__device__ __align__(256) float g_Yp[6400 * 512];        // yProj, row = t*256+b
__device__ __align__(256) float g_GIY[6400 * 1536];      // precomputed gi (yProj part + b_ih)
__device__ __align__(256) float g_states[26 * 256 * 512];// state0 .. state25
__device__ __align__(256) float g_C1[256 * 2048];        // [sProj | gh] per step
__device__ __align__(256) float g_GI[256 * 1536];        // gi per step
__device__ __align__(256) float g_ctx[256 * 512];        // attention context

// ---------------------------------------------------------------------------
// Generic guarded SGEMM (NT): C[m,n] = sum_k A[m,k]*W[n,k]  (+bias, +addend)
// 64x64 tile, BK=16, 256 threads, 4x4 per thread. Optional split-K via gridDim.z.
// ---------------------------------------------------------------------------
__global__ __launch_bounds__(256)
void sgemm64(const float* __restrict__ A, int lda,
             const float* __restrict__ W, int ldw,
             const float* __restrict__ bias,
             const float* __restrict__ addend, int ldadd,
             float* __restrict__ C, int ldc,
             int M, int N, int K, int Kc)
{
    __shared__ float As[16][68];   // padded: row stride 272B = 17*16B (aligned, low conflict)
    __shared__ float Ws[16][68];

    int tid = threadIdx.x;
    int tx = tid & 15, ty = tid >> 4;
    int m0 = blockIdx.y * 64, n0 = blockIdx.x * 64;

    int kstart = 0, kend = K;
    float* Cp = C;
    if (Kc > 0) {
        kstart = blockIdx.z * Kc;
        kend = min(K, kstart + Kc);
        Cp = C + (size_t)blockIdx.z * (size_t)M * (size_t)ldc;
    }

    float acc[4][4];
#pragma unroll
    for (int i = 0; i < 4; i++)
#pragma unroll
        for (int j = 0; j < 4; j++) acc[i][j] = 0.f;

    for (int k0 = kstart; k0 < kend; k0 += 16) {
#pragma unroll
        for (int i = 0; i < 4; i++) {
            int idx = tid + i * 256;
            int r = idx >> 4, kk = idx & 15;
            int gk = k0 + kk;
            int gm = m0 + r;
            As[kk][r] = (gm < M && gk < kend) ? A[(size_t)gm * lda + gk] : 0.f;
            int gn = n0 + r;
            Ws[kk][r] = (gn < N && gk < kend) ? W[(size_t)gn * ldw + gk] : 0.f;
        }
        __syncthreads();
#pragma unroll
        for (int kk = 0; kk < 16; kk++) {
            float4 a = *(const float4*)&As[kk][ty * 4];
            float4 b = *(const float4*)&Ws[kk][tx * 4];
            float av[4] = {a.x, a.y, a.z, a.w};
            float bv[4] = {b.x, b.y, b.z, b.w};
#pragma unroll
            for (int i = 0; i < 4; i++)
#pragma unroll
                for (int j = 0; j < 4; j++)
                    acc[i][j] = fmaf(av[i], bv[j], acc[i][j]);
        }
        __syncthreads();
    }

#pragma unroll
    for (int i = 0; i < 4; i++) {
        int m = m0 + ty * 4 + i;
        if (m >= M) continue;
#pragma unroll
        for (int j = 0; j < 4; j++) {
            int n = n0 + tx * 4 + j;
            if (n >= N) continue;
            float v = acc[i][j];
            if (bias)   v += bias[n];
            if (addend) v += addend[(size_t)m * ldadd + n];
            Cp[(size_t)m * ldc + n] = v;
        }
    }
}

// ---------------------------------------------------------------------------
// Big-tile SGEMM (NT): 128x128 tile, BK=8, 256 threads, 8x8 per thread.
// permuted=1: m=(t*256+b) row is scattered to out[b][t][n] (fc epilogue).
// ---------------------------------------------------------------------------
__global__ __launch_bounds__(256)
void sgemm128(const float* __restrict__ A, int lda,
              const float* __restrict__ W, int ldw,
              const float* __restrict__ bias,
              float* __restrict__ C, int ldc,
              int M, int N, int K, int permuted)
{
    __shared__ float As[8][128];
    __shared__ float Ws[8][128];

    int tid = threadIdx.x;
    int m0 = blockIdx.y * 128, n0 = blockIdx.x * 128;
    int lr = tid >> 1;            // 0..127 row within tile
    int lk = (tid & 1) * 4;       // 0 or 4
    int tx = tid & 15, ty = tid >> 4;

    float acc[8][8];
#pragma unroll
    for (int i = 0; i < 8; i++)
#pragma unroll
        for (int j = 0; j < 8; j++) acc[i][j] = 0.f;

    for (int k0 = 0; k0 < K; k0 += 8) {
        int gk = k0 + lk;
        {
            int gm = m0 + lr;
            float4 a = make_float4(0.f, 0.f, 0.f, 0.f);
            if (gm < M) {
                if (gk + 3 < K) a = *(const float4*)&A[(size_t)gm * lda + gk];
                else {
                    const float* p = &A[(size_t)gm * lda];
                    if (gk + 0 < K) a.x = p[gk + 0];
                    if (gk + 1 < K) a.y = p[gk + 1];
                    if (gk + 2 < K) a.z = p[gk + 2];
                    if (gk + 3 < K) a.w = p[gk + 3];
                }
            }
            As[lk + 0][lr] = a.x; As[lk + 1][lr] = a.y;
            As[lk + 2][lr] = a.z; As[lk + 3][lr] = a.w;
        }
        {
            int gn = n0 + lr;
            float4 b = make_float4(0.f, 0.f, 0.f, 0.f);
            if (gn < N) {
                if (gk + 3 < K) b = *(const float4*)&W[(size_t)gn * ldw + gk];
                else {
                    const float* p = &W[(size_t)gn * ldw];
                    if (gk + 0 < K) b.x = p[gk + 0];
                    if (gk + 1 < K) b.y = p[gk + 1];
                    if (gk + 2 < K) b.z = p[gk + 2];
                    if (gk + 3 < K) b.w = p[gk + 3];
                }
            }
            Ws[lk + 0][lr] = b.x; Ws[lk + 1][lr] = b.y;
            Ws[lk + 2][lr] = b.z; Ws[lk + 3][lr] = b.w;
        }
        __syncthreads();
#pragma unroll
        for (int kk = 0; kk < 8; kk++) {
            float4 a0 = *(const float4*)&As[kk][ty * 4];
            float4 a1 = *(const float4*)&As[kk][ty * 4 + 64];
            float4 b0 = *(const float4*)&Ws[kk][tx * 4];
            float4 b1 = *(const float4*)&Ws[kk][tx * 4 + 64];
            float av[8] = {a0.x, a0.y, a0.z, a0.w, a1.x, a1.y, a1.z, a1.w};
            float bv[8] = {b0.x, b0.y, b0.z, b0.w, b1.x, b1.y, b1.z, b1.w};
#pragma unroll
            for (int i = 0; i < 8; i++)
#pragma unroll
                for (int j = 0; j < 8; j++)
                    acc[i][j] = fmaf(av[i], bv[j], acc[i][j]);
        }
        __syncthreads();
    }

#pragma unroll
    for (int i = 0; i < 8; i++) {
        int m = m0 + ((i < 4) ? (ty * 4 + i) : (64 + ty * 4 + i - 4));
        if (m >= M) continue;
#pragma unroll
        for (int j = 0; j < 8; j++) {
            int n = n0 + ((j < 4) ? (tx * 4 + j) : (64 + tx * 4 + j - 4));
            if (n >= N) continue;
            float v = acc[i][j] + (bias ? bias[n] : 0.f);
            if (permuted) {
                int b = m & 255;
                int t = m >> 8;
                C[(size_t)b * (TDEC * YDIM_) + (size_t)t * YDIM_ + n] = v;
            } else {
                C[(size_t)m * ldc + n] = v;
            }
        }
    }
}

// ---------------------------------------------------------------------------
// Small helper kernels
// ---------------------------------------------------------------------------
__global__ void wcat_fill(const float* __restrict__ sEmbed_w,
                          const float* __restrict__ sEmbed_b,
                          const float* __restrict__ w_hh,
                          const float* __restrict__ b_hh)
{
    int idx = blockIdx.x * blockDim.x + threadIdx.x;
    if (idx < 2048 * 512) {
        int n = idx >> 9;
        g_Wcat[idx] = (n < 512) ? sEmbed_w[idx] : w_hh[idx - 512 * 512];
    }
    if (idx < 2048)
        g_bcat[idx] = (idx < 512) ? sEmbed_b[idx] : b_hh[idx - 512];
}

__global__ void splitk_reduce(const float* __restrict__ bias)
{
    int idx = blockIdx.x * blockDim.x + threadIdx.x;   // 256*300
    if (idx >= 256 * 300) return;
    float s = 0.f;
#pragma unroll
    for (int z = 0; z < 16; z++) s += g_EbufPart[z * (256 * 300) + idx];
    g_emb[idx] = s + bias[idx % 300];
}

__global__ void yp_gather(const int* __restrict__ targets,
                          const float* __restrict__ tgt_emb)
{
    int idx = blockIdx.x * blockDim.x + threadIdx.x;   // 25*256*512
    if (idx >= TDEC * 256 * 512) return;
    int d = idx & 511;
    int row = idx >> 9;          // t*256 + b
    int b = row & 255;
    int t = row >> 8;
    int y = (t == 0) ? YDIM_ : targets[b * TDEC + (t - 1)];
    g_Yp[idx] = tgt_emb[(size_t)y * 512 + d];
}

// Fused attention: e = tanh(sProj + xProj) . w + wb ; softmax over T=25; context.
// one block per batch element, 256 threads.
__global__ __launch_bounds__(256)
void attn_kernel(const float* __restrict__ x,
                 const float* __restrict__ wEmbed_w,
                 const float* __restrict__ wEmbed_b)
{
    int b = blockIdx.x;
    int tid = threadIdx.x;
    __shared__ float sP[512];
    __shared__ float red[256];
    __shared__ float alpha[32];

    sP[tid]       = g_C1[b * 2048 + tid];
    sP[tid + 256] = g_C1[b * 2048 + 256 + tid];
    float w0 = wEmbed_w[tid];
    float w1 = wEmbed_w[tid + 256];
    float wb = wEmbed_b[0];
    __syncthreads();

    for (int t = 0; t < TENC; t++) {
        const float* xp = g_XP + (size_t)(b * TENC + t) * 512;
        float v = w0 * tanhf(sP[tid] + xp[tid]) +
                  w1 * tanhf(sP[tid + 256] + xp[tid + 256]);
        red[tid] = v;
        __syncthreads();
#pragma unroll
        for (int s = 128; s > 0; s >>= 1) {
            if (tid < s) red[tid] += red[tid + s];
            __syncthreads();
        }
        if (tid == 0) alpha[t] = red[0] + wb;
        __syncthreads();
    }

    if (tid < 32) {
        float ev = (tid < TENC) ? alpha[tid] : -1e30f;
        float m = ev;
#pragma unroll
        for (int o = 16; o > 0; o >>= 1) m = fmaxf(m, __shfl_xor_sync(0xffffffffu, m, o));
        float ex = (tid < TENC) ? __expf(ev - m) : 0.f;
        float s = ex;
#pragma unroll
        for (int o = 16; o > 0; o >>= 1) s += __shfl_xor_sync(0xffffffffu, s, o);
        if (tid < TENC) alpha[tid] = ex / s;
    }
    __syncthreads();

    float c0 = 0.f, c1 = 0.f;
#pragma unroll
    for (int t = 0; t < TENC; t++) {
        const float* xr = x + (size_t)(b * TENC + t) * 512;
        float a = alpha[t];
        c0 = fmaf(a, xr[tid], c0);
        c1 = fmaf(a, xr[tid + 256], c1);
    }
    g_ctx[b * 512 + tid] = c0;
    g_ctx[b * 512 + 256 + tid] = c1;
}

// GRU gate fusion: reads g_GI (gi) and g_C1 (gh in cols 512..2047), updates state.
__global__ void gru_fuse(int t)
{
    int idx = blockIdx.x * blockDim.x + threadIdx.x;   // 256*512
    if (idx >= 256 * 512) return;
    int b = idx >> 9, j = idx & 511;
    const float* gi = g_GI + b * 1536;
    const float* gh = g_C1 + b * 2048 + 512;
    float ir = gi[j],        iz = gi[512 + j],  in_ = gi[1024 + j];
    float hr = gh[j],        hz = gh[512 + j],  hn  = gh[1024 + j];
    float r = 1.f / (1.f + __expf(-(ir + hr)));
    float z = 1.f / (1.f + __expf(-(iz + hz)));
    float n = tanhf(in_ + r * hn);
    const float* s_in  = g_states + (size_t)t * (256 * 512);
    float*       s_out = g_states + (size_t)(t + 1) * (256 * 512);
    s_out[idx] = (1.f - z) * n + z * s_in[idx];
}

// ---------------------------------------------------------------------------
// Launch
// ---------------------------------------------------------------------------
extern "C" void kernel_launch(void* const* d_in, const int* in_sizes, int n_in,
                              void* d_out, int out_size)
{
    int off = (n_in > 19) ? 1 : 0;   // 'lengths' scalar may or may not be passed
    const float* x          = (const float*)d_in[0];
    const int*   targets    = (const int*)  d_in[1];
    const float* eEmbed_w   = (const float*)d_in[2 + off];
    const float* eEmbed_b   = (const float*)d_in[3 + off];
    const float* embed_fc_w = (const float*)d_in[4 + off];
    const float* embed_fc_b = (const float*)d_in[5 + off];
    const float* sEmbed_w   = (const float*)d_in[6 + off];
    const float* sEmbed_b   = (const float*)d_in[7 + off];
    const float* xEmbed_w   = (const float*)d_in[8 + off];
    const float* xEmbed_b   = (const float*)d_in[9 + off];
    const float* wEmbed_w   = (const float*)d_in[10 + off];
    const float* wEmbed_b   = (const float*)d_in[11 + off];
    const float* tgt_emb    = (const float*)d_in[12 + off];
    const float* gru_w_ih   = (const float*)d_in[13 + off];
    const float* gru_w_hh   = (const float*)d_in[14 + off];
    const float* gru_b_ih   = (const float*)d_in[15 + off];
    const float* gru_b_hh   = (const float*)d_in[16 + off];
    const float* fc_w       = (const float*)d_in[17 + off];
    const float* fc_b       = (const float*)d_in[18 + off];
    float* out = (float*)d_out;

    float *pWcat, *pbcat, *pEbufPart, *pemb, *pXP, *pYp, *pGIY, *pstates, *pC1, *pGI, *pctx;
    cudaGetSymbolAddress((void**)&pWcat,     g_Wcat);
    cudaGetSymbolAddress((void**)&pbcat,     g_bcat);
    cudaGetSymbolAddress((void**)&pEbufPart, g_EbufPart);
    cudaGetSymbolAddress((void**)&pemb,      g_emb);
    cudaGetSymbolAddress((void**)&pXP,       g_XP);
    cudaGetSymbolAddress((void**)&pYp,       g_Yp);
    cudaGetSymbolAddress((void**)&pGIY,      g_GIY);
    cudaGetSymbolAddress((void**)&pstates,   g_states);
    cudaGetSymbolAddress((void**)&pC1,       g_C1);
    cudaGetSymbolAddress((void**)&pGI,       g_GI);
    cudaGetSymbolAddress((void**)&pctx,      g_ctx);

    // ---- Prologue (loop-invariant work) ----
    wcat_fill<<<4096, 256>>>(sEmbed_w, sEmbed_b, gru_w_hh, gru_b_hh);

    // embed = x_flat @ eEmbed_w.T  (K=12800, split-K 16-way, two-pass)
    sgemm64<<<dim3(5, 4, 16), 256>>>(x, TENC * XDIM_, eEmbed_w, TENC * XDIM_,
                                     nullptr, nullptr, 0,
                                     pEbufPart, 300, 256, 300, TENC * XDIM_, 800);
    splitk_reduce<<<300, 256>>>(eEmbed_b);

    // state0 = emb @ embed_fc_w.T  (K=300)
    sgemm64<<<dim3(8, 4), 256>>>(pemb, 300, embed_fc_w, 300, embed_fc_b,
                                 nullptr, 0, pstates, 512, 256, 512, 300, 0);

    // xProj = x @ xEmbed_w.T  (M=6400)
    sgemm128<<<dim3(4, 50), 256>>>(x, 512, xEmbed_w, 512, xEmbed_b,
                                   pXP, 512, 6400, 512, 512, 0);

    // yProj gather for all steps, then GIY = Yp @ w_ih[:, :512].T + b_ih  (M=6400)
    yp_gather<<<12800, 256>>>(targets, tgt_emb);
    sgemm128<<<dim3(12, 50), 256>>>(pYp, 512, gru_w_ih, 1024, gru_b_ih,
                                    pGIY, 1536, 6400, 1536, 512, 0);

    // ---- Sequential decode loop ----
    for (int t = 0; t < TDEC; t++) {
        const float* state_in = pstates + (size_t)t * (256 * 512);

        // [sProj | gh] = state @ [sEmbed_w ; w_hh].T
        sgemm64<<<dim3(32, 4), 256>>>(state_in, 512, pWcat, 512, pbcat,
                                      nullptr, 0, pC1, 2048, 256, 2048, 512, 0);

        // attention -> context
        attn_kernel<<<256, 256>>>(x, wEmbed_w, wEmbed_b);

        // gi = GIY[t] + context @ w_ih[:, 512:1024].T
        sgemm64<<<dim3(24, 4), 256>>>(pctx, 512, gru_w_ih + 512, 1024, nullptr,
                                      pGIY + (size_t)t * (256 * 1536), 1536,
                                      pGI, 1536, 256, 1536, 512, 0);

        // GRU gates -> states[t+1]
        gru_fuse<<<512, 256>>>(t);
    }

    // ---- Epilogue: batched fc over all 25 states, scattered to [B, T, Y] ----
    sgemm128<<<dim3(52, 50), 256>>>(pstates + 256 * 512, 512, fc_w, 512, fc_b,
                                    out, 0, 6400, YDIM_, 512, 1);
}

// round 2
// speedup vs baseline: 1.1249x; 1.1249x over previous
#include <cuda_runtime.h>
#include <cuda_bf16.h>
#include <mma.h>

using namespace nvcuda;

// Problem constants
#define BB      256
#define TENC    25
#define XDIM_   512
#define SDIM_   512
#define ADIM_   512
#define YDIM_   6625
#define TDEC    25
#define EMBIN   300

// ---------------------------------------------------------------------------
// Static device scratch (allocation-free rule: __device__ globals)
// ---------------------------------------------------------------------------
__device__ __align__(256) float g_Wcat[2048 * 512];      // [sEmbed_w ; gru_w_hh]
__device__ __align__(256) float g_bcat[2048];
__device__ __align__(256) float g_EbufPart[16 * 256 * 300];
__device__ __align__(256) float g_emb[256 * 300];
__device__ __align__(256) float g_XP[6400 * 512];        // xProj, row = b*25+t
__device__ __align__(256) float g_Yp[6400 * 512];        // yProj, row = t*256+b
__device__ __align__(256) float g_GIY[6400 * 1536];      // precomputed gi (yProj part + b_ih)
__device__ __align__(256) float g_states[26 * 256 * 512];// state0 .. state25
__device__ __align__(256) float g_C1[256 * 2048];        // [sProj | gh] per step
__device__ __align__(256) float g_GI[256 * 1536];        // gi per step
__device__ __align__(256) float g_ctx[256 * 512];        // attention context

// ---------------------------------------------------------------------------
// TF32 wmma GEMM (NT): C[m,n] = sum_k A[m,k]*W[n,k] + bias[n]
// Block tile 128x128, BK=32, 256 threads = 8 warps (2x4), warp tile 64x32.
// permuted=1: row m=(t*256+b) scattered to out[b][t][n] (fc epilogue).
// Requires K % 32 == 0, lda/ldw rows 16B-aligned.
// ---------------------------------------------------------------------------
__global__ __launch_bounds__(256)
void wgemm(const float* __restrict__ A, int lda,
           const float* __restrict__ W, int ldw,
           const float* __restrict__ bias,
           float* __restrict__ C, int ldc,
           int M, int N, int K, int permuted)
{
    __shared__ float sm[9216];          // 36 KB
    float* As = sm;                     // [128][36]
    float* Ws = sm + 4608;              // [128][36]
    const int LDS = 36;

    int tid  = threadIdx.x;
    int warp = tid >> 5;
    int wr   = warp >> 2;               // 0..1  (64-row half)
    int wc   = warp & 3;                // 0..3  (32-col slice)
    int m0 = blockIdx.y * 128;
    int n0 = blockIdx.x * 128;

    wmma::fragment<wmma::accumulator, 16, 16, 8, float> c_frag[4][2];
#pragma unroll
    for (int i = 0; i < 4; i++)
#pragma unroll
        for (int j = 0; j < 2; j++)
            wmma::fill_fragment(c_frag[i][j], 0.0f);

    for (int k0 = 0; k0 < K; k0 += 32) {
#pragma unroll
        for (int i = 0; i < 4; i++) {
            int idx = tid + i * 256;        // 0..1023
            int r = idx >> 3;               // 0..127
            int c4 = (idx & 7) * 4;         // 0..28
            float4 va = make_float4(0.f, 0.f, 0.f, 0.f);
            int gm = m0 + r;
            if (gm < M) va = *(const float4*)&A[(size_t)gm * lda + k0 + c4];
            *(float4*)&As[r * LDS + c4] = va;
            float4 vb = make_float4(0.f, 0.f, 0.f, 0.f);
            int gn = n0 + r;
            if (gn < N) vb = *(const float4*)&W[(size_t)gn * ldw + k0 + c4];
            *(float4*)&Ws[r * LDS + c4] = vb;
        }
        __syncthreads();

#pragma unroll
        for (int ks = 0; ks < 32; ks += 8) {
            wmma::fragment<wmma::matrix_a, 16, 16, 8, wmma::precision::tf32, wmma::row_major> a_frag[4];
            wmma::fragment<wmma::matrix_b, 16, 16, 8, wmma::precision::tf32, wmma::col_major> b_frag[2];
#pragma unroll
            for (int i = 0; i < 4; i++) {
                wmma::load_matrix_sync(a_frag[i], &As[(wr * 64 + i * 16) * LDS + ks], LDS);
#pragma unroll
                for (int t = 0; t < a_frag[i].num_elements; t++)
                    a_frag[i].x[t] = wmma::__float_to_tf32(a_frag[i].x[t]);
            }
#pragma unroll
            for (int j = 0; j < 2; j++) {
                wmma::load_matrix_sync(b_frag[j], &Ws[(wc * 32 + j * 16) * LDS + ks], LDS);
#pragma unroll
                for (int t = 0; t < b_frag[j].num_elements; t++)
                    b_frag[j].x[t] = wmma::__float_to_tf32(b_frag[j].x[t]);
            }
#pragma unroll
            for (int i = 0; i < 4; i++)
#pragma unroll
                for (int j = 0; j < 2; j++)
                    wmma::mma_sync(c_frag[i][j], a_frag[i], b_frag[j], c_frag[i][j]);
        }
        __syncthreads();
    }

    // Epilogue: stage each 64-row half through shared, then guarded global write.
    float* Cs = sm;                     // [64][132] = 8448 floats (fits in 9216)
    const int LDCS = 132;
#pragma unroll
    for (int p = 0; p < 2; p++) {
        if (wr == p) {
#pragma unroll
            for (int i = 0; i < 4; i++)
#pragma unroll
                for (int j = 0; j < 2; j++)
                    wmma::store_matrix_sync(&Cs[(i * 16) * LDCS + wc * 32 + j * 16],
                                            c_frag[i][j], LDCS, wmma::mem_row_major);
        }
        __syncthreads();
#pragma unroll
        for (int i = 0; i < 32; i++) {
            int idx = tid + i * 256;        // 0..8191
            int r = idx >> 7;               // 0..63
            int c = idx & 127;
            int m = m0 + p * 64 + r;
            int n = n0 + c;
            if (m < M && n < N) {
                float v = Cs[r * LDCS + c] + (bias ? bias[n] : 0.f);
                if (permuted) {
                    int b = m & 255;
                    int t = m >> 8;
                    C[(size_t)b * (TDEC * YDIM_) + (size_t)t * YDIM_ + n] = v;
                } else {
                    C[(size_t)m * ldc + n] = v;
                }
            }
        }
        __syncthreads();
    }
}

// ---------------------------------------------------------------------------
// Generic guarded SGEMM (NT): C[m,n] = sum_k A[m,k]*W[n,k]  (+bias, +addend)
// 64x64 tile, BK=16, 256 threads, 4x4 per thread. Optional split-K via gridDim.z.
// Used for the fp32-precision recurrence path + prologue odds and ends.
// ---------------------------------------------------------------------------
__global__ __launch_bounds__(256)
void sgemm64(const float* __restrict__ A, int lda,
             const float* __restrict__ W, int ldw,
             const float* __restrict__ bias,
             const float* __restrict__ addend, int ldadd,
             float* __restrict__ C, int ldc,
             int M, int N, int K, int Kc)
{
    __shared__ float As[16][68];
    __shared__ float Ws[16][68];

    int tid = threadIdx.x;
    int tx = tid & 15, ty = tid >> 4;
    int m0 = blockIdx.y * 64, n0 = blockIdx.x * 64;

    int kstart = 0, kend = K;
    float* Cp = C;
    if (Kc > 0) {
        kstart = blockIdx.z * Kc;
        kend = min(K, kstart + Kc);
        Cp = C + (size_t)blockIdx.z * (size_t)M * (size_t)ldc;
    }

    float acc[4][4];
#pragma unroll
    for (int i = 0; i < 4; i++)
#pragma unroll
        for (int j = 0; j < 4; j++) acc[i][j] = 0.f;

    for (int k0 = kstart; k0 < kend; k0 += 16) {
#pragma unroll
        for (int i = 0; i < 4; i++) {
            int idx = tid + i * 256;
            int r = idx >> 4, kk = idx & 15;
            int gk = k0 + kk;
            int gm = m0 + r;
            As[kk][r] = (gm < M && gk < kend) ? A[(size_t)gm * lda + gk] : 0.f;
            int gn = n0 + r;
            Ws[kk][r] = (gn < N && gk < kend) ? W[(size_t)gn * ldw + gk] : 0.f;
        }
        __syncthreads();
#pragma unroll
        for (int kk = 0; kk < 16; kk++) {
            float4 a = *(const float4*)&As[kk][ty * 4];
            float4 b = *(const float4*)&Ws[kk][tx * 4];
            float av[4] = {a.x, a.y, a.z, a.w};
            float bv[4] = {b.x, b.y, b.z, b.w};
#pragma unroll
            for (int i = 0; i < 4; i++)
#pragma unroll
                for (int j = 0; j < 4; j++)
                    acc[i][j] = fmaf(av[i], bv[j], acc[i][j]);
        }
        __syncthreads();
    }

#pragma unroll
    for (int i = 0; i < 4; i++) {
        int m = m0 + ty * 4 + i;
        if (m >= M) continue;
#pragma unroll
        for (int j = 0; j < 4; j++) {
            int n = n0 + tx * 4 + j;
            if (n >= N) continue;
            float v = acc[i][j];
            if (bias)   v += bias[n];
            if (addend) v += addend[(size_t)m * ldadd + n];
            Cp[(size_t)m * ldc + n] = v;
        }
    }
}

// ---------------------------------------------------------------------------
// Small helper kernels
// ---------------------------------------------------------------------------
__global__ void wcat_fill(const float* __restrict__ sEmbed_w,
                          const float* __restrict__ sEmbed_b,
                          const float* __restrict__ w_hh,
                          const float* __restrict__ b_hh)
{
    int idx = blockIdx.x * blockDim.x + threadIdx.x;
    if (idx < 2048 * 512) {
        int n = idx >> 9;
        g_Wcat[idx] = (n < 512) ? sEmbed_w[idx] : w_hh[idx - 512 * 512];
    }
    if (idx < 2048)
        g_bcat[idx] = (idx < 512) ? sEmbed_b[idx] : b_hh[idx - 512];
}

__global__ void splitk_reduce(const float* __restrict__ bias)
{
    int idx = blockIdx.x * blockDim.x + threadIdx.x;   // 256*300
    if (idx >= 256 * 300) return;
    float s = 0.f;
#pragma unroll
    for (int z = 0; z < 16; z++) s += g_EbufPart[z * (256 * 300) + idx];
    g_emb[idx] = s + bias[idx % 300];
}

__global__ void yp_gather(const int* __restrict__ targets,
                          const float* __restrict__ tgt_emb)
{
    int idx = blockIdx.x * blockDim.x + threadIdx.x;   // 25*256*512
    if (idx >= TDEC * 256 * 512) return;
    int d = idx & 511;
    int row = idx >> 9;          // t*256 + b
    int b = row & 255;
    int t = row >> 8;
    int y = (t == 0) ? YDIM_ : targets[b * TDEC + (t - 1)];
    g_Yp[idx] = tgt_emb[(size_t)y * 512 + d];
}

// Fused attention: e = tanh(sProj + xProj) . w + wb ; softmax over T=25; context.
__global__ __launch_bounds__(256)
void attn_kernel(const float* __restrict__ x,
                 const float* __restrict__ wEmbed_w,
                 const float* __restrict__ wEmbed_b)
{
    int b = blockIdx.x;
    int tid = threadIdx.x;
    __shared__ float sP[512];
    __shared__ float red[256];
    __shared__ float alpha[32];

    sP[tid]       = g_C1[b * 2048 + tid];
    sP[tid + 256] = g_C1[b * 2048 + 256 + tid];
    float w0 = wEmbed_w[tid];
    float w1 = wEmbed_w[tid + 256];
    float wb = wEmbed_b[0];
    __syncthreads();

    for (int t = 0; t < TENC; t++) {
        const float* xp = g_XP + (size_t)(b * TENC + t) * 512;
        float v = w0 * tanhf(sP[tid] + xp[tid]) +
                  w1 * tanhf(sP[tid + 256] + xp[tid + 256]);
        red[tid] = v;
        __syncthreads();
#pragma unroll
        for (int s = 128; s > 0; s >>= 1) {
            if (tid < s) red[tid] += red[tid + s];
            __syncthreads();
        }
        if (tid == 0) alpha[t] = red[0] + wb;
        __syncthreads();
    }

    if (tid < 32) {
        float ev = (tid < TENC) ? alpha[tid] : -1e30f;
        float m = ev;
#pragma unroll
        for (int o = 16; o > 0; o >>= 1) m = fmaxf(m, __shfl_xor_sync(0xffffffffu, m, o));
        float ex = (tid < TENC) ? __expf(ev - m) : 0.f;
        float s = ex;
#pragma unroll
        for (int o = 16; o > 0; o >>= 1) s += __shfl_xor_sync(0xffffffffu, s, o);
        if (tid < TENC) alpha[tid] = ex / s;
    }
    __syncthreads();

    float c0 = 0.f, c1 = 0.f;
#pragma unroll
    for (int t = 0; t < TENC; t++) {
        const float* xr = x + (size_t)(b * TENC + t) * 512;
        float a = alpha[t];
        c0 = fmaf(a, xr[tid], c0);
        c1 = fmaf(a, xr[tid + 256], c1);
    }
    g_ctx[b * 512 + tid] = c0;
    g_ctx[b * 512 + 256 + tid] = c1;
}

// GRU gate fusion: reads g_GI (gi) and g_C1 (gh in cols 512..2047), updates state.
__global__ void gru_fuse(int t)
{
    int idx = blockIdx.x * blockDim.x + threadIdx.x;   // 256*512
    if (idx >= 256 * 512) return;
    int b = idx >> 9, j = idx & 511;
    const float* gi = g_GI + b * 1536;
    const float* gh = g_C1 + b * 2048 + 512;
    float ir = gi[j],        iz = gi[512 + j],  in_ = gi[1024 + j];
    float hr = gh[j],        hz = gh[512 + j],  hn  = gh[1024 + j];
    float r = 1.f / (1.f + __expf(-(ir + hr)));
    float z = 1.f / (1.f + __expf(-(iz + hz)));
    float n = tanhf(in_ + r * hn);
    const float* s_in  = g_states + (size_t)t * (256 * 512);
    float*       s_out = g_states + (size_t)(t + 1) * (256 * 512);
    s_out[idx] = (1.f - z) * n + z * s_in[idx];
}

// ---------------------------------------------------------------------------
// Launch
// ---------------------------------------------------------------------------
extern "C" void kernel_launch(void* const* d_in, const int* in_sizes, int n_in,
                              void* d_out, int out_size)
{
    int off = (n_in > 19) ? 1 : 0;   // 'lengths' scalar may or may not be passed
    const float* x          = (const float*)d_in[0];
    const int*   targets    = (const int*)  d_in[1];
    const float* eEmbed_w   = (const float*)d_in[2 + off];
    const float* eEmbed_b   = (const float*)d_in[3 + off];
    const float* embed_fc_w = (const float*)d_in[4 + off];
    const float* embed_fc_b = (const float*)d_in[5 + off];
    const float* sEmbed_w   = (const float*)d_in[6 + off];
    const float* sEmbed_b   = (const float*)d_in[7 + off];
    const float* xEmbed_w   = (const float*)d_in[8 + off];
    const float* xEmbed_b   = (const float*)d_in[9 + off];
    const float* wEmbed_w   = (const float*)d_in[10 + off];
    const float* wEmbed_b   = (const float*)d_in[11 + off];
    const float* tgt_emb    = (const float*)d_in[12 + off];
    const float* gru_w_ih   = (const float*)d_in[13 + off];
    const float* gru_w_hh   = (const float*)d_in[14 + off];
    const float* gru_b_ih   = (const float*)d_in[15 + off];
    const float* gru_b_hh   = (const float*)d_in[16 + off];
    const float* fc_w       = (const float*)d_in[17 + off];
    const float* fc_b       = (const float*)d_in[18 + off];
    float* out = (float*)d_out;

    float *pWcat, *pbcat, *pEbufPart, *pemb, *pXP, *pYp, *pGIY, *pstates, *pC1, *pGI, *pctx;
    cudaGetSymbolAddress((void**)&pWcat,     g_Wcat);
    cudaGetSymbolAddress((void**)&pbcat,     g_bcat);
    cudaGetSymbolAddress((void**)&pEbufPart, g_EbufPart);
    cudaGetSymbolAddress((void**)&pemb,      g_emb);
    cudaGetSymbolAddress((void**)&pXP,       g_XP);
    cudaGetSymbolAddress((void**)&pYp,       g_Yp);
    cudaGetSymbolAddress((void**)&pGIY,      g_GIY);
    cudaGetSymbolAddress((void**)&pstates,   g_states);
    cudaGetSymbolAddress((void**)&pC1,       g_C1);
    cudaGetSymbolAddress((void**)&pGI,       g_GI);
    cudaGetSymbolAddress((void**)&pctx,      g_ctx);

    // ---- Prologue (loop-invariant work) ----
    wcat_fill<<<4096, 256>>>(sEmbed_w, sEmbed_b, gru_w_hh, gru_b_hh);

    // embed = x_flat @ eEmbed_w.T  (K=12800, split-K 16-way, two-pass, fp32)
    sgemm64<<<dim3(5, 4, 16), 256>>>(x, TENC * XDIM_, eEmbed_w, TENC * XDIM_,
                                     nullptr, nullptr, 0,
                                     pEbufPart, 300, 256, 300, TENC * XDIM_, 800);
    splitk_reduce<<<300, 256>>>(eEmbed_b);

    // state0 = emb @ embed_fc_w.T  (K=300, fp32)
    sgemm64<<<dim3(8, 4), 256>>>(pemb, 300, embed_fc_w, 300, embed_fc_b,
                                 nullptr, 0, pstates, 512, 256, 512, 300, 0);

    // xProj = x @ xEmbed_w.T  (M=6400, TF32 tensor cores)
    wgemm<<<dim3(4, 50), 256>>>(x, 512, xEmbed_w, 512, xEmbed_b,
                                pXP, 512, 6400, 512, 512, 0);

    // yProj gather for all steps, then GIY = Yp @ w_ih[:, :512].T + b_ih (TF32)
    yp_gather<<<12800, 256>>>(targets, tgt_emb);
    wgemm<<<dim3(12, 50), 256>>>(pYp, 512, gru_w_ih, 1024, gru_b_ih,
                                 pGIY, 1536, 6400, 1536, 512, 0);

    // ---- Sequential decode loop (fp32 precision path) ----
    for (int t = 0; t < TDEC; t++) {
        const float* state_in = pstates + (size_t)t * (256 * 512);

        // [sProj | gh] = state @ [sEmbed_w ; w_hh].T
        sgemm64<<<dim3(32, 4), 256>>>(state_in, 512, pWcat, 512, pbcat,
                                      nullptr, 0, pC1, 2048, 256, 2048, 512, 0);

        // attention -> context
        attn_kernel<<<256, 256>>>(x, wEmbed_w, wEmbed_b);

        // gi = GIY[t] + context @ w_ih[:, 512:1024].T
        sgemm64<<<dim3(24, 4), 256>>>(pctx, 512, gru_w_ih + 512, 1024, nullptr,
                                      pGIY + (size_t)t * (256 * 1536), 1536,
                                      pGI, 1536, 256, 1536, 512, 0);

        // GRU gates -> states[t+1]
        gru_fuse<<<512, 256>>>(t);
    }

    // ---- Epilogue: batched fc over all 25 states (TF32), scattered to [B,T,Y] ----
    wgemm<<<dim3(52, 50), 256>>>(pstates + 256 * 512, 512, fc_w, 512, fc_b,
                                 out, 0, 6400, YDIM_, 512, 1);
}

// round 8
// speedup vs baseline: 1.3752x; 1.2225x over previous
#include <cstdint>
#include <cuda_runtime.h>
#include <cuda_bf16.h>
#include <mma.h>

using namespace nvcuda;

// Problem constants
#define BB      256
#define TENC    25
#define XDIM_   512
#define SDIM_   512
#define ADIM_   512
#define YDIM_   6625
#define TDEC    25
#define EMBIN   300

// ---------------------------------------------------------------------------
// Static device scratch
// ---------------------------------------------------------------------------
__device__ __align__(256) float g_Wcat[2048 * 512];      // [sEmbed_w ; gru_w_hh]
__device__ __align__(256) float g_bcat[2048];
__device__ __align__(256) float g_EbufPart[16 * 256 * 300];
__device__ __align__(256) float g_emb[256 * 300];
__device__ __align__(256) float g_XP[6400 * 512];        // xProj, row = b*25+t
__device__ __align__(256) float g_Yp[6400 * 512];        // yProj, row = t*256+b
__device__ __align__(256) float g_GIY[6400 * 1536];      // precomputed gi (yProj part + b_ih)
__device__ __align__(256) float g_states[26 * 256 * 512];// state0 .. state25
__device__ __align__(256) float g_C1[256 * 2048];        // [sProj | gh] per step
__device__ __align__(256) float g_GI[256 * 1536];        // gi per step
__device__ __align__(256) float g_ctx[256 * 512];        // attention context

// ---------------------------------------------------------------------------
// cp.async helpers
// ---------------------------------------------------------------------------
__device__ __forceinline__ void cp_async16(void* smem_dst, const void* gptr, bool pred)
{
    unsigned int sa = (unsigned int)__cvta_generic_to_shared(smem_dst);
    int bytes = pred ? 16 : 0;
    asm volatile("cp.async.ca.shared.global [%0], [%1], 16, %2;\n"
                 :: "r"(sa), "l"(gptr), "r"(bytes));
}

// ---------------------------------------------------------------------------
// Pipelined TF32 wmma GEMM (NT): C = A @ W^T + bias. Block 128x128, BK=16,
// 2-stage cp.async double buffering, 8 warps (2x4), warp tile 64x32.
// Requires M % 128 == 0, K % 16 == 0. N guarded.
// permuted=1: row m=(t*256+b) scattered to out[b][t][n].
// ---------------------------------------------------------------------------
__global__ __launch_bounds__(256)
void wgemm(const float* __restrict__ A, int lda,
           const float* __restrict__ W, int ldw,
           const float* __restrict__ bias,
           float* __restrict__ C, int ldc,
           int M, int N, int K, int permuted)
{
    __shared__ float sm[10240];     // 40 KB
    const int LDS = 20;
    // stage s: A at s*5120, W at s*5120 + 2560  ([128][20] each)

    int tid  = threadIdx.x;
    int warp = tid >> 5;
    int wr   = warp >> 2;           // 0..1
    int wc   = warp & 3;            // 0..3
    int m0 = blockIdx.y * 128;
    int n0 = blockIdx.x * 128;

    wmma::fragment<wmma::accumulator, 16, 16, 8, float> c_frag[4][2];
#pragma unroll
    for (int i = 0; i < 4; i++)
#pragma unroll
        for (int j = 0; j < 2; j++)
            wmma::fill_fragment(c_frag[i][j], 0.0f);

    int nIter = K >> 4;

    // stage loader: 128 rows x 16 cols per matrix, 2 float4 per thread per matrix
    auto load_stage = [&](int k0, int s) {
        float* As = sm + s * 5120;
        float* Ws = sm + s * 5120 + 2560;
#pragma unroll
        for (int i = 0; i < 2; i++) {
            int idx = tid + i * 256;
            int r  = idx >> 2;
            int c4 = (idx & 3) * 4;
            cp_async16(&As[r * LDS + c4], &A[(size_t)(m0 + r) * lda + k0 + c4], true);
            int gn = n0 + r;
            cp_async16(&Ws[r * LDS + c4], &W[(size_t)gn * ldw + k0 + c4], gn < N);
        }
        asm volatile("cp.async.commit_group;\n");
    };

    load_stage(0, 0);

    for (int it = 0; it < nIter; it++) {
        if (it + 1 < nIter) {
            load_stage((it + 1) << 4, (it + 1) & 1);
            asm volatile("cp.async.wait_group 1;\n");
        } else {
            asm volatile("cp.async.wait_group 0;\n");
        }
        __syncthreads();

        float* As = sm + (it & 1) * 5120;
        float* Ws = sm + (it & 1) * 5120 + 2560;
#pragma unroll
        for (int ks = 0; ks < 16; ks += 8) {
            wmma::fragment<wmma::matrix_a, 16, 16, 8, wmma::precision::tf32, wmma::row_major> a_frag[4];
            wmma::fragment<wmma::matrix_b, 16, 16, 8, wmma::precision::tf32, wmma::col_major> b_frag[2];
#pragma unroll
            for (int i = 0; i < 4; i++) {
                wmma::load_matrix_sync(a_frag[i], &As[(wr * 64 + i * 16) * LDS + ks], LDS);
#pragma unroll
                for (int t = 0; t < a_frag[i].num_elements; t++)
                    a_frag[i].x[t] = wmma::__float_to_tf32(a_frag[i].x[t]);
            }
#pragma unroll
            for (int j = 0; j < 2; j++) {
                wmma::load_matrix_sync(b_frag[j], &Ws[(wc * 32 + j * 16) * LDS + ks], LDS);
#pragma unroll
                for (int t = 0; t < b_frag[j].num_elements; t++)
                    b_frag[j].x[t] = wmma::__float_to_tf32(b_frag[j].x[t]);
            }
#pragma unroll
            for (int i = 0; i < 4; i++)
#pragma unroll
                for (int j = 0; j < 2; j++)
                    wmma::mma_sync(c_frag[i][j], a_frag[i], b_frag[j], c_frag[i][j]);
        }
        __syncthreads();
    }

    // Epilogue: stage each 64-row half through shared, then guarded global write.
    float* Cs = sm;                 // [64][132] = 8448 floats (fits in 10240)
    const int LDCS = 132;
#pragma unroll
    for (int p = 0; p < 2; p++) {
        if (wr == p) {
#pragma unroll
            for (int i = 0; i < 4; i++)
#pragma unroll
                for (int j = 0; j < 2; j++)
                    wmma::store_matrix_sync(&Cs[(i * 16) * LDCS + wc * 32 + j * 16],
                                            c_frag[i][j], LDCS, wmma::mem_row_major);
        }
        __syncthreads();
#pragma unroll
        for (int i = 0; i < 32; i++) {
            int idx = tid + i * 256;
            int r = idx >> 7;
            int c = idx & 127;
            int m = m0 + p * 64 + r;
            int n = n0 + c;
            if (n < N) {
                float v = Cs[r * LDCS + c] + (bias ? bias[n] : 0.f);
                if (permuted) {
                    int b = m & 255;
                    int t = m >> 8;
                    C[(size_t)b * (TDEC * YDIM_) + (size_t)t * YDIM_ + n] = v;
                } else {
                    C[(size_t)m * ldc + n] = v;
                }
            }
        }
        __syncthreads();
    }
}

// ---------------------------------------------------------------------------
// Small TF32 wmma GEMM (NT) for the decode loop: block 64x64, 4 warps (2x2),
// warp tile 32x32, BK=32. Requires M%64==0, N%64==0, K%32==0 (all satisfied).
// C = A @ W^T (+bias[n]) (+addend[m][n]).
// ---------------------------------------------------------------------------
__global__ __launch_bounds__(128)
void wgemm_small(const float* __restrict__ A, int lda,
                 const float* __restrict__ W, int ldw,
                 const float* __restrict__ bias,
                 const float* __restrict__ addend, int ldadd,
                 float* __restrict__ C, int ldc, int K)
{
    __shared__ float sm[4608];
    const int LDS = 36;
    float* As = sm;                 // [64][36]
    float* Ws = sm + 2304;

    int tid  = threadIdx.x;
    int warp = tid >> 5;
    int wr   = warp >> 1;           // 0..1
    int wc   = warp & 1;            // 0..1
    int m0 = blockIdx.y * 64;
    int n0 = blockIdx.x * 64;

    wmma::fragment<wmma::accumulator, 16, 16, 8, float> c_frag[2][2];
#pragma unroll
    for (int i = 0; i < 2; i++)
#pragma unroll
        for (int j = 0; j < 2; j++)
            wmma::fill_fragment(c_frag[i][j], 0.0f);

    for (int k0 = 0; k0 < K; k0 += 32) {
#pragma unroll
        for (int i = 0; i < 4; i++) {
            int idx = tid + i * 128;        // 0..511
            int r  = idx >> 3;              // 0..63
            int c4 = (idx & 7) * 4;         // 0..28
            *(float4*)&As[r * LDS + c4] = *(const float4*)&A[(size_t)(m0 + r) * lda + k0 + c4];
            *(float4*)&Ws[r * LDS + c4] = *(const float4*)&W[(size_t)(n0 + r) * ldw + k0 + c4];
        }
        __syncthreads();
#pragma unroll
        for (int ks = 0; ks < 32; ks += 8) {
            wmma::fragment<wmma::matrix_a, 16, 16, 8, wmma::precision::tf32, wmma::row_major> a_frag[2];
            wmma::fragment<wmma::matrix_b, 16, 16, 8, wmma::precision::tf32, wmma::col_major> b_frag[2];
#pragma unroll
            for (int i = 0; i < 2; i++) {
                wmma::load_matrix_sync(a_frag[i], &As[(wr * 32 + i * 16) * LDS + ks], LDS);
#pragma unroll
                for (int t = 0; t < a_frag[i].num_elements; t++)
                    a_frag[i].x[t] = wmma::__float_to_tf32(a_frag[i].x[t]);
            }
#pragma unroll
            for (int j = 0; j < 2; j++) {
                wmma::load_matrix_sync(b_frag[j], &Ws[(wc * 32 + j * 16) * LDS + ks], LDS);
#pragma unroll
                for (int t = 0; t < b_frag[j].num_elements; t++)
                    b_frag[j].x[t] = wmma::__float_to_tf32(b_frag[j].x[t]);
            }
#pragma unroll
            for (int i = 0; i < 2; i++)
#pragma unroll
                for (int j = 0; j < 2; j++)
                    wmma::mma_sync(c_frag[i][j], a_frag[i], b_frag[j], c_frag[i][j]);
        }
        __syncthreads();
    }

    // Epilogue via shared staging
    float* Cs = sm;                 // [64][68] = 4352 floats
    const int LDCS = 68;
#pragma unroll
    for (int i = 0; i < 2; i++)
#pragma unroll
        for (int j = 0; j < 2; j++)
            wmma::store_matrix_sync(&Cs[(wr * 32 + i * 16) * LDCS + wc * 32 + j * 16],
                                    c_frag[i][j], LDCS, wmma::mem_row_major);
    __syncthreads();
#pragma unroll
    for (int i = 0; i < 32; i++) {
        int idx = tid + i * 128;            // 0..4095
        int r = idx >> 6;
        int c = idx & 63;
        int m = m0 + r, n = n0 + c;
        float v = Cs[r * LDCS + c];
        if (bias)   v += bias[n];
        if (addend) v += addend[(size_t)m * ldadd + n];
        C[(size_t)m * ldc + n] = v;
    }
}

// ---------------------------------------------------------------------------
// fp32 SGEMM 64x64 (prologue only: embed split-K, state0)
// ---------------------------------------------------------------------------
__global__ __launch_bounds__(256)
void sgemm64(const float* __restrict__ A, int lda,
             const float* __restrict__ W, int ldw,
             const float* __restrict__ bias,
             const float* __restrict__ addend, int ldadd,
             float* __restrict__ C, int ldc,
             int M, int N, int K, int Kc)
{
    __shared__ float As[16][68];
    __shared__ float Ws[16][68];

    int tid = threadIdx.x;
    int tx = tid & 15, ty = tid >> 4;
    int m0 = blockIdx.y * 64, n0 = blockIdx.x * 64;

    int kstart = 0, kend = K;
    float* Cp = C;
    if (Kc > 0) {
        kstart = blockIdx.z * Kc;
        kend = min(K, kstart + Kc);
        Cp = C + (size_t)blockIdx.z * (size_t)M * (size_t)ldc;
    }

    float acc[4][4];
#pragma unroll
    for (int i = 0; i < 4; i++)
#pragma unroll
        for (int j = 0; j < 4; j++) acc[i][j] = 0.f;

    for (int k0 = kstart; k0 < kend; k0 += 16) {
#pragma unroll
        for (int i = 0; i < 4; i++) {
            int idx = tid + i * 256;
            int r = idx >> 4, kk = idx & 15;
            int gk = k0 + kk;
            int gm = m0 + r;
            As[kk][r] = (gm < M && gk < kend) ? A[(size_t)gm * lda + gk] : 0.f;
            int gn = n0 + r;
            Ws[kk][r] = (gn < N && gk < kend) ? W[(size_t)gn * ldw + gk] : 0.f;
        }
        __syncthreads();
#pragma unroll
        for (int kk = 0; kk < 16; kk++) {
            float4 a = *(const float4*)&As[kk][ty * 4];
            float4 b = *(const float4*)&Ws[kk][tx * 4];
            float av[4] = {a.x, a.y, a.z, a.w};
            float bv[4] = {b.x, b.y, b.z, b.w};
#pragma unroll
            for (int i = 0; i < 4; i++)
#pragma unroll
                for (int j = 0; j < 4; j++)
                    acc[i][j] = fmaf(av[i], bv[j], acc[i][j]);
        }
        __syncthreads();
    }

#pragma unroll
    for (int i = 0; i < 4; i++) {
        int m = m0 + ty * 4 + i;
        if (m >= M) continue;
#pragma unroll
        for (int j = 0; j < 4; j++) {
            int n = n0 + tx * 4 + j;
            if (n >= N) continue;
            float v = acc[i][j];
            if (bias)   v += bias[n];
            if (addend) v += addend[(size_t)m * ldadd + n];
            Cp[(size_t)m * ldc + n] = v;
        }
    }
}

// ---------------------------------------------------------------------------
// Small helper kernels
// ---------------------------------------------------------------------------
__global__ void wcat_fill(const float* __restrict__ sEmbed_w,
                          const float* __restrict__ sEmbed_b,
                          const float* __restrict__ w_hh,
                          const float* __restrict__ b_hh)
{
    int idx = blockIdx.x * blockDim.x + threadIdx.x;
    if (idx < 2048 * 512) {
        int n = idx >> 9;
        g_Wcat[idx] = (n < 512) ? sEmbed_w[idx] : w_hh[idx - 512 * 512];
    }
    if (idx < 2048)
        g_bcat[idx] = (idx < 512) ? sEmbed_b[idx] : b_hh[idx - 512];
}

__global__ void splitk_reduce(const float* __restrict__ bias)
{
    int idx = blockIdx.x * blockDim.x + threadIdx.x;   // 256*300
    if (idx >= 256 * 300) return;
    float s = 0.f;
#pragma unroll
    for (int z = 0; z < 16; z++) s += g_EbufPart[z * (256 * 300) + idx];
    g_emb[idx] = s + bias[idx % 300];
}

__global__ void yp_gather(const int* __restrict__ targets,
                          const float* __restrict__ tgt_emb)
{
    int idx = blockIdx.x * blockDim.x + threadIdx.x;   // 25*256*512
    if (idx >= TDEC * 256 * 512) return;
    int d = idx & 511;
    int row = idx >> 9;          // t*256 + b
    int b = row & 255;
    int t = row >> 8;
    int y = (t == 0) ? YDIM_ : targets[b * TDEC + (t - 1)];
    g_Yp[idx] = tgt_emb[(size_t)y * 512 + d];
}

// Fused attention with warp-shuffle reductions.
__global__ __launch_bounds__(256)
void attn_kernel(const float* __restrict__ x,
                 const float* __restrict__ wEmbed_w,
                 const float* __restrict__ wEmbed_b)
{
    int b = blockIdx.x;
    int tid = threadIdx.x;
    int lane = tid & 31, warp = tid >> 5;
    __shared__ float sP[512];
    __shared__ float wsum[8];
    __shared__ float alpha[32];

    sP[tid]       = g_C1[b * 2048 + tid];
    sP[tid + 256] = g_C1[b * 2048 + 256 + tid];
    float w0 = wEmbed_w[tid];
    float w1 = wEmbed_w[tid + 256];
    float wb = wEmbed_b[0];
    __syncthreads();

    for (int t = 0; t < TENC; t++) {
        const float* xp = g_XP + (size_t)(b * TENC + t) * 512;
        float v = w0 * tanhf(sP[tid] + xp[tid]) +
                  w1 * tanhf(sP[tid + 256] + xp[tid + 256]);
#pragma unroll
        for (int o = 16; o > 0; o >>= 1) v += __shfl_xor_sync(0xffffffffu, v, o);
        if (lane == 0) wsum[warp] = v;
        __syncthreads();
        if (warp == 0) {
            float s = (lane < 8) ? wsum[lane] : 0.f;
#pragma unroll
            for (int o = 4; o > 0; o >>= 1) s += __shfl_xor_sync(0xffffffffu, s, o);
            if (lane == 0) alpha[t] = s + wb;
        }
        __syncthreads();
    }

    if (tid < 32) {
        float ev = (tid < TENC) ? alpha[tid] : -1e30f;
        float m = ev;
#pragma unroll
        for (int o = 16; o > 0; o >>= 1) m = fmaxf(m, __shfl_xor_sync(0xffffffffu, m, o));
        float ex = (tid < TENC) ? __expf(ev - m) : 0.f;
        float s = ex;
#pragma unroll
        for (int o = 16; o > 0; o >>= 1) s += __shfl_xor_sync(0xffffffffu, s, o);
        if (tid < TENC) alpha[tid] = ex / s;
    }
    __syncthreads();

    float c0 = 0.f, c1 = 0.f;
#pragma unroll
    for (int t = 0; t < TENC; t++) {
        const float* xr = x + (size_t)(b * TENC + t) * 512;
        float a = alpha[t];
        c0 = fmaf(a, xr[tid], c0);
        c1 = fmaf(a, xr[tid + 256], c1);
    }
    g_ctx[b * 512 + tid] = c0;
    g_ctx[b * 512 + 256 + tid] = c1;
}

// GRU gate fusion
__global__ void gru_fuse(int t)
{
    int idx = blockIdx.x * blockDim.x + threadIdx.x;   // 256*512
    if (idx >= 256 * 512) return;
    int b = idx >> 9, j = idx & 511;
    const float* gi = g_GI + b * 1536;
    const float* gh = g_C1 + b * 2048 + 512;
    float ir = gi[j],        iz = gi[512 + j],  in_ = gi[1024 + j];
    float hr = gh[j],        hz = gh[512 + j],  hn  = gh[1024 + j];
    float r = 1.f / (1.f + __expf(-(ir + hr)));
    float z = 1.f / (1.f + __expf(-(iz + hz)));
    float n = tanhf(in_ + r * hn);
    const float* s_in  = g_states + (size_t)t * (256 * 512);
    float*       s_out = g_states + (size_t)(t + 1) * (256 * 512);
    s_out[idx] = (1.f - z) * n + z * s_in[idx];
}

// ---------------------------------------------------------------------------
// Launch
// ---------------------------------------------------------------------------
extern "C" void kernel_launch(void* const* d_in, const int* in_sizes, int n_in,
                              void* d_out, int out_size)
{
    int off = (n_in > 19) ? 1 : 0;
    const float* x          = (const float*)d_in[0];
    const int*   targets    = (const int*)  d_in[1];
    const float* eEmbed_w   = (const float*)d_in[2 + off];
    const float* eEmbed_b   = (const float*)d_in[3 + off];
    const float* embed_fc_w = (const float*)d_in[4 + off];
    const float* embed_fc_b = (const float*)d_in[5 + off];
    const float* sEmbed_w   = (const float*)d_in[6 + off];
    const float* sEmbed_b   = (const float*)d_in[7 + off];
    const float* xEmbed_w   = (const float*)d_in[8 + off];
    const float* xEmbed_b   = (const float*)d_in[9 + off];
    const float* wEmbed_w   = (const float*)d_in[10 + off];
    const float* wEmbed_b   = (const float*)d_in[11 + off];
    const float* tgt_emb    = (const float*)d_in[12 + off];
    const float* gru_w_ih   = (const float*)d_in[13 + off];
    const float* gru_w_hh   = (const float*)d_in[14 + off];
    const float* gru_b_ih   = (const float*)d_in[15 + off];
    const float* gru_b_hh   = (const float*)d_in[16 + off];
    const float* fc_w       = (const float*)d_in[17 + off];
    const float* fc_b       = (const float*)d_in[18 + off];
    float* out = (float*)d_out;

    float *pWcat, *pbcat, *pEbufPart, *pemb, *pXP, *pYp, *pGIY, *pstates, *pC1, *pGI, *pctx;
    cudaGetSymbolAddress((void**)&pWcat,     g_Wcat);
    cudaGetSymbolAddress((void**)&pbcat,     g_bcat);
    cudaGetSymbolAddress((void**)&pEbufPart, g_EbufPart);
    cudaGetSymbolAddress((void**)&pemb,      g_emb);
    cudaGetSymbolAddress((void**)&pXP,       g_XP);
    cudaGetSymbolAddress((void**)&pYp,       g_Yp);
    cudaGetSymbolAddress((void**)&pGIY,      g_GIY);
    cudaGetSymbolAddress((void**)&pstates,   g_states);
    cudaGetSymbolAddress((void**)&pC1,       g_C1);
    cudaGetSymbolAddress((void**)&pGI,       g_GI);
    cudaGetSymbolAddress((void**)&pctx,      g_ctx);

    // ---- Prologue (loop-invariant work) ----
    wcat_fill<<<4096, 256>>>(sEmbed_w, sEmbed_b, gru_w_hh, gru_b_hh);

    // embed = x_flat @ eEmbed_w.T  (K=12800, split-K 16-way, fp32)
    sgemm64<<<dim3(5, 4, 16), 256>>>(x, TENC * XDIM_, eEmbed_w, TENC * XDIM_,
                                     nullptr, nullptr, 0,
                                     pEbufPart, 300, 256, 300, TENC * XDIM_, 800);
    splitk_reduce<<<300, 256>>>(eEmbed_b);

    // state0 = emb @ embed_fc_w.T  (K=300, fp32)
    sgemm64<<<dim3(8, 4), 256>>>(pemb, 300, embed_fc_w, 300, embed_fc_b,
                                 nullptr, 0, pstates, 512, 256, 512, 300, 0);

    // xProj = x @ xEmbed_w.T  (TF32 pipelined)
    wgemm<<<dim3(4, 50), 256>>>(x, 512, xEmbed_w, 512, xEmbed_b,
                                pXP, 512, 6400, 512, 512, 0);

    // yProj gather, then GIY = Yp @ w_ih[:, :512].T + b_ih (TF32 pipelined)
    yp_gather<<<12800, 256>>>(targets, tgt_emb);
    wgemm<<<dim3(12, 50), 256>>>(pYp, 512, gru_w_ih, 1024, gru_b_ih,
                                 pGIY, 1536, 6400, 1536, 512, 0);

    // ---- Sequential decode loop (TF32 tensor cores) ----
    for (int t = 0; t < TDEC; t++) {
        const float* state_in = pstates + (size_t)t * (256 * 512);

        // [sProj | gh] = state @ [sEmbed_w ; w_hh].T   (256 x 2048 x 512)
        wgemm_small<<<dim3(32, 4), 128>>>(state_in, 512, pWcat, 512, pbcat,
                                          nullptr, 0, pC1, 2048, 512);

        // attention -> context
        attn_kernel<<<256, 256>>>(x, wEmbed_w, wEmbed_b);

        // gi = GIY[t] + context @ w_ih[:, 512:1024].T  (256 x 1536 x 512)
        wgemm_small<<<dim3(24, 4), 128>>>(pctx, 512, gru_w_ih + 512, 1024, nullptr,
                                          pGIY + (size_t)t * (256 * 1536), 1536,
                                          pGI, 1536, 512);

        // GRU gates -> states[t+1]
        gru_fuse<<<512, 256>>>(t);
    }

    // ---- Epilogue: batched fc over all 25 states (TF32 pipelined) ----
    wgemm<<<dim3(52, 50), 256>>>(pstates + 256 * 512, 512, fc_w, 512, fc_b,
                                 out, 0, 6400, YDIM_, 512, 1);
}